// round 14
// baseline (speedup 1.0000x reference)
#include <cuda_runtime.h>
#include <cstdint>
#include <cstddef>

#define B_   8
#define N_   512
#define FIN  128
#define FOUT 64
#define ALPHA 0.2f

// Scratch (no allocations allowed)
__device__ float g_Wh[B_ * N_ * FOUT];      // 1 MB
__device__ float g_ei[B_ * N_];
__device__ float g_ej[B_ * N_];
__device__ float g_part[4 * B_ * N_ * FOUT]; // 4 MB partial numerators [js][b*N+i][o]
__device__ float g_dsum[4 * B_ * N_];        // partial denominators   [js][b*N+i]

// ---------------------------------------------------------------------------
// Stage 1: Wh = h @ W ; e_i = Wh·a_i ; e_j = Wh·a_j
// Grid: 512 CTAs x 256 thr, 8 rows/CTA. Thread = (o-quad, row, k-half):
// 4 outputs via float4 W loads, half k-range each; halves combined in smem.
// ---------------------------------------------------------------------------
__global__ __launch_bounds__(256)
void gat_stage1(const float* __restrict__ h,
                const float* __restrict__ W,
                const float* __restrict__ a)
{
    __shared__ float  W_s[FIN * FOUT];   // 32 KB natural [k][o]
    __shared__ float  h_s[8 * FIN];      // 4 KB
    __shared__ float4 part_s[256];       // 4 KB k-half partials
    __shared__ float  wh_s[8 * FOUT];    // 2 KB

    const int t  = threadIdx.x;
    const int b  = blockIdx.x >> 6;          // 64 tiles per batch
    const int i0 = (blockIdx.x & 63) * 8;

    {
        const float4* W4g = (const float4*)W;
        float4* Ws4 = (float4*)W_s;
        #pragma unroll
        for (int r = 0; r < 8; r++) Ws4[t + r * 256] = W4g[t + r * 256];
        const float4* hb = (const float4*)(h + ((size_t)(b * N_ + i0)) * FIN);
        ((float4*)h_s)[t] = hb[t];           // 256 float4 = 8x128 floats
    }
    __syncthreads();

    const int oq  = t & 15;                  // o quad: o = oq*4..oq*4+3
    const int row = (t >> 4) & 7;
    const int kh  = t >> 7;                  // k half: [kh*64, kh*64+64)
    float4 acc = make_float4(0.f, 0.f, 0.f, 0.f);
    const float*  hrow   = h_s + row * FIN + kh * 64;
    const float4* wbase4 = ((const float4*)W_s) + (kh * 64) * 16 + oq;
    #pragma unroll 8
    for (int k = 0; k < 64; k++) {
        float4 w4 = wbase4[k * 16];
        float  hv = hrow[k];
        acc.x = fmaf(hv, w4.x, acc.x);
        acc.y = fmaf(hv, w4.y, acc.y);
        acc.z = fmaf(hv, w4.z, acc.z);
        acc.w = fmaf(hv, w4.w, acc.w);
    }
    part_s[t] = acc;
    __syncthreads();

    if (t < 128) {                            // combine k-halves
        float4 p0 = part_s[t], p1 = part_s[t + 128];
        float4 r  = make_float4(p0.x + p1.x, p0.y + p1.y,
                                p0.z + p1.z, p0.w + p1.w);
        const int rw = t >> 4, q = t & 15;
        ((float4*)wh_s)[rw * 16 + q] = r;
        *(float4*)&g_Wh[((size_t)(b * N_ + i0 + rw)) * FOUT + q * 4] = r;
    }
    __syncthreads();

    const int wid = t >> 5, lane = t & 31;
    {
        int r = wid;                          // 8 warps, 8 rows
        float v1 = wh_s[r * FOUT + lane];
        float v2 = wh_s[r * FOUT + lane + 32];
        float si = v1 * a[lane]      + v2 * a[lane + 32];
        float sj = v1 * a[64 + lane] + v2 * a[96 + lane];
        #pragma unroll
        for (int off = 16; off > 0; off >>= 1) {
            si += __shfl_xor_sync(0xffffffffu, si, off);
            sj += __shfl_xor_sync(0xffffffffu, sj, off);
        }
        if (lane == 0) {
            g_ei[b * N_ + i0 + r] = si;
            g_ej[b * N_ + i0 + r] = sj;
        }
    }
}

// ---------------------------------------------------------------------------
// Stage 2: j-split fused stream. Grid = 8b x 128 itile x 4 js = 4096 CTAs,
// 256 threads, TI=4, j-range 128 per CTA (warp owns 16 j = 16 chunks of 1KB).
// Writes PARTIAL numerators/denominators; combine kernel finishes softmax.
// ---------------------------------------------------------------------------
#define TI 4

__device__ __forceinline__ void cp_async16(uint32_t dst, const float* src) {
    asm volatile("cp.async.cg.shared.global [%0], [%1], 16;"
                 :: "r"(dst), "l"(src) : "memory");
}

__global__ __launch_bounds__(256, 4)
void gat_stage2(const float* __restrict__ edge,
                const float* __restrict__ U,
                const float* __restrict__ a)
{
    __shared__ __align__(16) float pool_s[8 * 4 * 256];   // ring 32 KB / red_w 8 KB
    __shared__ float  ej_s[128];
    __shared__ float4 u_s[16];
    __shared__ float  ei_s[TI];
    __shared__ float  wsum[TI * 8];

    const int t    = threadIdx.x;
    const int js   = blockIdx.x & 3;
    const int rest = blockIdx.x >> 2;
    const int b    = rest >> 7;               // 128 i-tiles per batch (TI=4)
    const int i0   = (rest & 127) * TI;
    const int wid  = t >> 5, lane = t & 31;
    const int g3   = lane >> 3, s8 = lane & 7;

    const float a_e = __ldg(a + 2 * FOUT);
    if (t < 16) {
        float4 u = ((const float4*)U)[t];
        u.x *= a_e; u.y *= a_e; u.z *= a_e; u.w *= a_e;
        u_s[t] = u;
    }
    if (t < TI) ei_s[t] = g_ei[b * N_ + i0 + t];
    if (t < 128) ej_s[t] = g_ej[b * N_ + js * 128 + t];
    __syncthreads();

    const float4 u4a = u_s[s8];
    const float4 u4b = u_s[s8 + 8];
    const float* WhB = g_Wh + (size_t)b * N_ * FOUT;
    const int jbg = js * 128 + wid * 16;      // warp's global j base

    const float* wbase = edge + ((size_t)(b * N_ + i0) * N_ + jbg) * FOUT;
    const uint32_t stg =
        (uint32_t)__cvta_generic_to_shared(&pool_s[wid * 1024]) + lane * 16;

    // prologue: chunks 0,1,2 (sub=0, ti=0..2)
    #pragma unroll
    for (int c = 0; c < 3; c++) {
        const float* gsrc = wbase + c * (N_ * FOUT) + lane * 4;
        uint32_t dst = stg + c * 1024;
        cp_async16(dst,       gsrc);
        cp_async16(dst + 512, gsrc + 128);
        asm volatile("cp.async.commit_group;" ::: "memory");
    }

    float acc0[TI], acc1[TI], psum[TI];
    #pragma unroll
    for (int ti = 0; ti < TI; ti++) { acc0[ti] = 0.f; acc1[ti] = 0.f; psum[ti] = 0.f; }

    // preload Wh rows for sub = 0
    float whA[4], whB4[4];
    #pragma unroll
    for (int k = 0; k < 4; k++) {
        const float* wr = WhB + (size_t)(jbg + k) * FOUT;
        whA[k]  = __ldg(wr + lane);
        whB4[k] = __ldg(wr + lane + 32);
    }

    for (int sub = 0; sub < 4; sub++) {
        const float ejv = ej_s[wid * 16 + sub * 4 + g3];

        #pragma unroll
        for (int ti = 0; ti < TI; ti++) {
            const int c = sub * 4 + ti;
            if (c < 13) {
                const int cn = c + 3;
                const int subn = cn >> 2, tin = cn & 3;
                const float* gsrc = wbase + tin * (N_ * FOUT)
                                          + subn * (4 * FOUT) + lane * 4;
                uint32_t dst = stg + (cn & 3) * 1024;
                cp_async16(dst,       gsrc);
                cp_async16(dst + 512, gsrc + 128);
                asm volatile("cp.async.commit_group;" ::: "memory");
                asm volatile("cp.async.wait_group 3;" ::: "memory");
            } else if (c == 13) {
                asm volatile("cp.async.wait_group 2;" ::: "memory");
            } else if (c == 14) {
                asm volatile("cp.async.wait_group 1;" ::: "memory");
            } else {
                asm volatile("cp.async.wait_group 0;" ::: "memory");
            }
            __syncwarp();

            const float4* buf = (const float4*)&pool_s[wid * 1024 + (c & 3) * 256];
            float4 v0 = buf[g3 * 16 + s8];
            float4 v1 = buf[g3 * 16 + s8 + 8];
            float s = v0.x * u4a.x + v0.y * u4a.y + v0.z * u4a.z + v0.w * u4a.w
                    + v1.x * u4b.x + v1.y * u4b.y + v1.z * u4b.z + v1.w * u4b.w;
            #pragma unroll
            for (int off = 4; off > 0; off >>= 1)
                s += __shfl_xor_sync(0xffffffffu, s, off);
            float val = ei_s[ti] + ejv + s;
            val = fmaxf(val, ALPHA * val);      // leaky relu (alpha > 0)
            float ev = __expf(val);
            if (s8 == 0) psum[ti] += ev;
            #pragma unroll
            for (int k = 0; k < 4; k++) {
                float evk = __shfl_sync(0xffffffffu, ev, k * 8);
                acc0[ti] = fmaf(evk, whA[k],  acc0[ti]);
                acc1[ti] = fmaf(evk, whB4[k], acc1[ti]);
            }
            __syncwarp();
        }

        // prefetch Wh rows for sub+1
        if (sub < 3) {
            #pragma unroll
            for (int k = 0; k < 4; k++) {
                const float* wr = WhB + (size_t)(jbg + (sub + 1) * 4 + k) * FOUT;
                whA[k]  = __ldg(wr + lane);
                whB4[k] = __ldg(wr + lane + 32);
            }
        }
    }
    __syncthreads();          // streaming done -> pool_s becomes red_w

    float* red_w = pool_s;    // [warp][ti][o]  8 KB
    #pragma unroll
    for (int ti = 0; ti < TI; ti++) {
        red_w[(wid * TI + ti) * FOUT + lane]      = acc0[ti];
        red_w[(wid * TI + ti) * FOUT + lane + 32] = acc1[ti];
        float p = psum[ti];
        p += __shfl_xor_sync(0xffffffffu, p, 8);
        p += __shfl_xor_sync(0xffffffffu, p, 16);
        if (lane == 0) wsum[ti * 8 + wid] = p;
    }
    __syncthreads();

    if (t < TI) {
        float ss = wsum[t * 8 + 0];
        #pragma unroll
        for (int w = 1; w < 8; w++) ss += wsum[t * 8 + w];
        g_dsum[js * (B_ * N_) + b * N_ + i0 + t] = ss;
    }

    // write partial numerators: 256 values, 1 per thread
    {
        const int ti = t >> 6, o = t & 63;
        float r = 0.f;
        #pragma unroll
        for (int w = 0; w < 8; w++)
            r += red_w[(w * TI + ti) * FOUT + o];
        g_part[(size_t)js * (B_ * N_ * FOUT)
               + (size_t)(b * N_ + i0 + ti) * FOUT + o] = r;
    }
}

// ---------------------------------------------------------------------------
// Stage 3: combine 4 j-split partials, normalize.
// Grid 512 x 256 threads, 2 outputs/thread.
// ---------------------------------------------------------------------------
__global__ __launch_bounds__(256)
void gat_combine(float* __restrict__ out)
{
    #pragma unroll
    for (int rep = 0; rep < 2; rep++) {
        int idx = blockIdx.x * 512 + rep * 256 + threadIdx.x;
        int row = idx >> 6;
        float num = 0.f, den = 0.f;
        #pragma unroll
        for (int js = 0; js < 4; js++) {
            num += g_part[(size_t)js * (B_ * N_ * FOUT) + idx];
            den += g_dsum[js * (B_ * N_) + row];
        }
        out[idx] = num * __frcp_rn(den);
    }
}

// ---------------------------------------------------------------------------
extern "C" void kernel_launch(void* const* d_in, const int* in_sizes, int n_in,
                              void* d_out, int out_size)
{
    const float* h    = (const float*)d_in[0];   // [8,512,128]
    const float* edge = (const float*)d_in[1];   // [8,512,512,64]
    const float* W    = (const float*)d_in[2];   // [1,128,64]
    const float* U    = (const float*)d_in[3];   // [1,64]
    const float* a    = (const float*)d_in[4];   // [1,129]
    float* out = (float*)d_out;                  // [8,512,64]

    gat_stage1<<<B_ * (N_ / 8), 256>>>(h, W, a);
    gat_stage2<<<B_ * (N_ / TI) * 4, 256>>>(edge, U, a);
    gat_combine<<<512, 256>>>(out);
}

// round 15
// speedup vs baseline: 1.2038x; 1.2038x over previous
#include <cuda_runtime.h>
#include <cstdint>
#include <cstddef>

#define B_   8
#define N_   512
#define FIN  128
#define FOUT 64
#define ALPHA 0.2f

// Scratch (no allocations allowed)
__device__ float g_Wh[B_ * N_ * FOUT];      // 1 MB
__device__ float g_ei[B_ * N_];
__device__ float g_ej[B_ * N_];
__device__ float g_part[4 * B_ * N_ * FOUT]; // 4 MB partial numerators [js][b*N+i][o]
__device__ float g_dsum[4 * B_ * N_];        // partial denominators   [js][b*N+i]

// ---------------------------------------------------------------------------
// Stage 1: Wh = h @ W ; e_i = Wh·a_i ; e_j = Wh·a_j
// Grid: 128 CTAs x 256 thr, 32 rows/CTA. Register-blocked GEMM:
// thread = 2 rows x 4 o; k4-step = 2 LDS.128 (h) + 4 LDS.128 (W) + 32 FMA.
// wh reduction buffer aliases h_s (dead after the k-loop).
// ---------------------------------------------------------------------------
__global__ __launch_bounds__(256)
void gat_stage1(const float* __restrict__ h,
                const float* __restrict__ W,
                const float* __restrict__ a)
{
    __shared__ float W_s[FIN * FOUT];    // 32 KB natural [k][o]
    __shared__ float h_s[32 * FIN];      // 16 KB ; aliased as wh[32][65] later

    const int t  = threadIdx.x;
    const int b  = blockIdx.x >> 4;          // 16 tiles per batch
    const int i0 = (blockIdx.x & 15) * 32;

    {
        const float4* W4g = (const float4*)W;
        float4* Ws4 = (float4*)W_s;
        #pragma unroll
        for (int r = 0; r < 8; r++) Ws4[t + r * 256] = W4g[t + r * 256];
        const float4* hb = (const float4*)(h + ((size_t)(b * N_ + i0)) * FIN);
        float4* hs4 = (float4*)h_s;
        #pragma unroll
        for (int r = 0; r < 4; r++) hs4[t + r * 256] = hb[t + r * 256];
    }
    __syncthreads();

    const int oq = t & 15;                   // o = oq*4 .. oq*4+3
    const int rp = t >> 4;                   // row pair: rows rp*2, rp*2+1
    float4 acc0 = make_float4(0.f, 0.f, 0.f, 0.f);
    float4 acc1 = make_float4(0.f, 0.f, 0.f, 0.f);
    const float4* W4  = (const float4*)W_s;                     // [k][oq]
    const float4* h4a = (const float4*)(h_s + (rp * 2) * FIN);
    const float4* h4b = (const float4*)(h_s + (rp * 2 + 1) * FIN);
    #pragma unroll 4
    for (int k4 = 0; k4 < 32; k4++) {
        float4 ha = h4a[k4];
        float4 hb = h4b[k4];
        float4 w0 = W4[(k4 * 4 + 0) * 16 + oq];
        float4 w1 = W4[(k4 * 4 + 1) * 16 + oq];
        float4 w2 = W4[(k4 * 4 + 2) * 16 + oq];
        float4 w3 = W4[(k4 * 4 + 3) * 16 + oq];
        acc0.x = fmaf(ha.x, w0.x, acc0.x); acc0.y = fmaf(ha.x, w0.y, acc0.y);
        acc0.z = fmaf(ha.x, w0.z, acc0.z); acc0.w = fmaf(ha.x, w0.w, acc0.w);
        acc0.x = fmaf(ha.y, w1.x, acc0.x); acc0.y = fmaf(ha.y, w1.y, acc0.y);
        acc0.z = fmaf(ha.y, w1.z, acc0.z); acc0.w = fmaf(ha.y, w1.w, acc0.w);
        acc0.x = fmaf(ha.z, w2.x, acc0.x); acc0.y = fmaf(ha.z, w2.y, acc0.y);
        acc0.z = fmaf(ha.z, w2.z, acc0.z); acc0.w = fmaf(ha.z, w2.w, acc0.w);
        acc0.x = fmaf(ha.w, w3.x, acc0.x); acc0.y = fmaf(ha.w, w3.y, acc0.y);
        acc0.z = fmaf(ha.w, w3.z, acc0.z); acc0.w = fmaf(ha.w, w3.w, acc0.w);
        acc1.x = fmaf(hb.x, w0.x, acc1.x); acc1.y = fmaf(hb.x, w0.y, acc1.y);
        acc1.z = fmaf(hb.x, w0.z, acc1.z); acc1.w = fmaf(hb.x, w0.w, acc1.w);
        acc1.x = fmaf(hb.y, w1.x, acc1.x); acc1.y = fmaf(hb.y, w1.y, acc1.y);
        acc1.z = fmaf(hb.y, w1.z, acc1.z); acc1.w = fmaf(hb.y, w1.w, acc1.w);
        acc1.x = fmaf(hb.z, w2.x, acc1.x); acc1.y = fmaf(hb.z, w2.y, acc1.y);
        acc1.z = fmaf(hb.z, w2.z, acc1.z); acc1.w = fmaf(hb.z, w2.w, acc1.w);
        acc1.x = fmaf(hb.w, w3.x, acc1.x); acc1.y = fmaf(hb.w, w3.y, acc1.y);
        acc1.z = fmaf(hb.w, w3.z, acc1.z); acc1.w = fmaf(hb.w, w3.w, acc1.w);
    }
    __syncthreads();                          // h_s dead -> reuse as wh[32][65]

    float* wh_s = h_s;
    {
        const int r0 = rp * 2, r1 = rp * 2 + 1, oc = oq * 4;
        wh_s[r0 * 65 + oc + 0] = acc0.x; wh_s[r0 * 65 + oc + 1] = acc0.y;
        wh_s[r0 * 65 + oc + 2] = acc0.z; wh_s[r0 * 65 + oc + 3] = acc0.w;
        wh_s[r1 * 65 + oc + 0] = acc1.x; wh_s[r1 * 65 + oc + 1] = acc1.y;
        wh_s[r1 * 65 + oc + 2] = acc1.z; wh_s[r1 * 65 + oc + 3] = acc1.w;
        *(float4*)&g_Wh[((size_t)(b * N_ + i0 + r0)) * FOUT + oc] = acc0;
        *(float4*)&g_Wh[((size_t)(b * N_ + i0 + r1)) * FOUT + oc] = acc1;
    }
    __syncthreads();

    const int wid = t >> 5, lane = t & 31;
    #pragma unroll
    for (int rr = 0; rr < 4; rr++) {
        int row = wid * 4 + rr;
        float v1 = wh_s[row * 65 + lane];
        float v2 = wh_s[row * 65 + lane + 32];
        float si = v1 * a[lane]      + v2 * a[lane + 32];
        float sj = v1 * a[64 + lane] + v2 * a[96 + lane];
        #pragma unroll
        for (int off = 16; off > 0; off >>= 1) {
            si += __shfl_xor_sync(0xffffffffu, si, off);
            sj += __shfl_xor_sync(0xffffffffu, sj, off);
        }
        if (lane == 0) {
            g_ei[b * N_ + i0 + row] = si;
            g_ej[b * N_ + i0 + row] = sj;
        }
    }
}

// ---------------------------------------------------------------------------
// Stage 2: j-split fused stream. Grid = 8b x 128 itile x 4 js = 4096 CTAs,
// 256 threads, TI=4, j-range 128 per CTA (warp owns 16 j = 16 chunks of 1KB).
// Writes PARTIAL numerators/denominators; combine kernel finishes softmax.
// ---------------------------------------------------------------------------
#define TI 4

__device__ __forceinline__ void cp_async16(uint32_t dst, const float* src) {
    asm volatile("cp.async.cg.shared.global [%0], [%1], 16;"
                 :: "r"(dst), "l"(src) : "memory");
}

__global__ __launch_bounds__(256, 4)
void gat_stage2(const float* __restrict__ edge,
                const float* __restrict__ U,
                const float* __restrict__ a)
{
    __shared__ __align__(16) float pool_s[8 * 4 * 256];   // ring 32 KB / red_w 8 KB
    __shared__ float  ej_s[128];
    __shared__ float4 u_s[16];
    __shared__ float  ei_s[TI];
    __shared__ float  wsum[TI * 8];

    const int t    = threadIdx.x;
    const int js   = blockIdx.x & 3;
    const int rest = blockIdx.x >> 2;
    const int b    = rest >> 7;               // 128 i-tiles per batch (TI=4)
    const int i0   = (rest & 127) * TI;
    const int wid  = t >> 5, lane = t & 31;
    const int g3   = lane >> 3, s8 = lane & 7;

    const float a_e = __ldg(a + 2 * FOUT);
    if (t < 16) {
        float4 u = ((const float4*)U)[t];
        u.x *= a_e; u.y *= a_e; u.z *= a_e; u.w *= a_e;
        u_s[t] = u;
    }
    if (t < TI) ei_s[t] = g_ei[b * N_ + i0 + t];
    if (t < 128) ej_s[t] = g_ej[b * N_ + js * 128 + t];
    __syncthreads();

    const float4 u4a = u_s[s8];
    const float4 u4b = u_s[s8 + 8];
    const float* WhB = g_Wh + (size_t)b * N_ * FOUT;
    const int jbg = js * 128 + wid * 16;      // warp's global j base

    const float* wbase = edge + ((size_t)(b * N_ + i0) * N_ + jbg) * FOUT;
    const uint32_t stg =
        (uint32_t)__cvta_generic_to_shared(&pool_s[wid * 1024]) + lane * 16;

    // prologue: chunks 0,1,2 (sub=0, ti=0..2)
    #pragma unroll
    for (int c = 0; c < 3; c++) {
        const float* gsrc = wbase + c * (N_ * FOUT) + lane * 4;
        uint32_t dst = stg + c * 1024;
        cp_async16(dst,       gsrc);
        cp_async16(dst + 512, gsrc + 128);
        asm volatile("cp.async.commit_group;" ::: "memory");
    }

    float acc0[TI], acc1[TI], psum[TI];
    #pragma unroll
    for (int ti = 0; ti < TI; ti++) { acc0[ti] = 0.f; acc1[ti] = 0.f; psum[ti] = 0.f; }

    // preload Wh rows for sub = 0
    float whA[4], whB4[4];
    #pragma unroll
    for (int k = 0; k < 4; k++) {
        const float* wr = WhB + (size_t)(jbg + k) * FOUT;
        whA[k]  = __ldg(wr + lane);
        whB4[k] = __ldg(wr + lane + 32);
    }

    for (int sub = 0; sub < 4; sub++) {
        const float ejv = ej_s[wid * 16 + sub * 4 + g3];

        #pragma unroll
        for (int ti = 0; ti < TI; ti++) {
            const int c = sub * 4 + ti;
            if (c < 13) {
                const int cn = c + 3;
                const int subn = cn >> 2, tin = cn & 3;
                const float* gsrc = wbase + tin * (N_ * FOUT)
                                          + subn * (4 * FOUT) + lane * 4;
                uint32_t dst = stg + (cn & 3) * 1024;
                cp_async16(dst,       gsrc);
                cp_async16(dst + 512, gsrc + 128);
                asm volatile("cp.async.commit_group;" ::: "memory");
                asm volatile("cp.async.wait_group 3;" ::: "memory");
            } else if (c == 13) {
                asm volatile("cp.async.wait_group 2;" ::: "memory");
            } else if (c == 14) {
                asm volatile("cp.async.wait_group 1;" ::: "memory");
            } else {
                asm volatile("cp.async.wait_group 0;" ::: "memory");
            }
            __syncwarp();

            const float4* buf = (const float4*)&pool_s[wid * 1024 + (c & 3) * 256];
            float4 v0 = buf[g3 * 16 + s8];
            float4 v1 = buf[g3 * 16 + s8 + 8];
            float s = v0.x * u4a.x + v0.y * u4a.y + v0.z * u4a.z + v0.w * u4a.w
                    + v1.x * u4b.x + v1.y * u4b.y + v1.z * u4b.z + v1.w * u4b.w;
            #pragma unroll
            for (int off = 4; off > 0; off >>= 1)
                s += __shfl_xor_sync(0xffffffffu, s, off);
            float val = ei_s[ti] + ejv + s;
            val = fmaxf(val, ALPHA * val);      // leaky relu (alpha > 0)
            float ev = __expf(val);
            if (s8 == 0) psum[ti] += ev;
            #pragma unroll
            for (int k = 0; k < 4; k++) {
                float evk = __shfl_sync(0xffffffffu, ev, k * 8);
                acc0[ti] = fmaf(evk, whA[k],  acc0[ti]);
                acc1[ti] = fmaf(evk, whB4[k], acc1[ti]);
            }
            __syncwarp();
        }

        // prefetch Wh rows for sub+1
        if (sub < 3) {
            #pragma unroll
            for (int k = 0; k < 4; k++) {
                const float* wr = WhB + (size_t)(jbg + (sub + 1) * 4 + k) * FOUT;
                whA[k]  = __ldg(wr + lane);
                whB4[k] = __ldg(wr + lane + 32);
            }
        }
    }
    __syncthreads();          // streaming done -> pool_s becomes red_w

    float* red_w = pool_s;    // [warp][ti][o]  8 KB
    #pragma unroll
    for (int ti = 0; ti < TI; ti++) {
        red_w[(wid * TI + ti) * FOUT + lane]      = acc0[ti];
        red_w[(wid * TI + ti) * FOUT + lane + 32] = acc1[ti];
        float p = psum[ti];
        p += __shfl_xor_sync(0xffffffffu, p, 8);
        p += __shfl_xor_sync(0xffffffffu, p, 16);
        if (lane == 0) wsum[ti * 8 + wid] = p;
    }
    __syncthreads();

    if (t < TI) {
        float ss = wsum[t * 8 + 0];
        #pragma unroll
        for (int w = 1; w < 8; w++) ss += wsum[t * 8 + w];
        g_dsum[js * (B_ * N_) + b * N_ + i0 + t] = ss;
    }

    // write partial numerators: 256 values, 1 per thread
    {
        const int ti = t >> 6, o = t & 63;
        float r = 0.f;
        #pragma unroll
        for (int w = 0; w < 8; w++)
            r += red_w[(w * TI + ti) * FOUT + o];
        g_part[(size_t)js * (B_ * N_ * FOUT)
               + (size_t)(b * N_ + i0 + ti) * FOUT + o] = r;
    }
}

// ---------------------------------------------------------------------------
// Stage 3: combine 4 j-split partials, normalize.
// Grid 512 x 256 threads, 2 outputs/thread.
// ---------------------------------------------------------------------------
__global__ __launch_bounds__(256)
void gat_combine(float* __restrict__ out)
{
    #pragma unroll
    for (int rep = 0; rep < 2; rep++) {
        int idx = blockIdx.x * 512 + rep * 256 + threadIdx.x;
        int row = idx >> 6;
        float num = 0.f, den = 0.f;
        #pragma unroll
        for (int js = 0; js < 4; js++) {
            num += g_part[(size_t)js * (B_ * N_ * FOUT) + idx];
            den += g_dsum[js * (B_ * N_) + row];
        }
        out[idx] = num * __frcp_rn(den);
    }
}

// ---------------------------------------------------------------------------
extern "C" void kernel_launch(void* const* d_in, const int* in_sizes, int n_in,
                              void* d_out, int out_size)
{
    const float* h    = (const float*)d_in[0];   // [8,512,128]
    const float* edge = (const float*)d_in[1];   // [8,512,512,64]
    const float* W    = (const float*)d_in[2];   // [1,128,64]
    const float* U    = (const float*)d_in[3];   // [1,64]
    const float* a    = (const float*)d_in[4];   // [1,129]
    float* out = (float*)d_out;                  // [8,512,64]

    gat_stage1<<<B_ * (N_ / 32), 256>>>(h, W, a);
    gat_stage2<<<B_ * (N_ / TI) * 4, 256>>>(edge, U, a);
    gat_combine<<<512, 256>>>(out);
}